// round 2
// baseline (speedup 1.0000x reference)
#include <cuda_runtime.h>
#include <cstdint>

#define BATCH 128
#define NPRI  8732
#define NOBJ  16
#define NCLS  21
#define NEGPOS 3
#define THRESH 0.5f

// ---------------- scratch (static device globals; no allocation) -------------
__device__ float   g_ce[BATCH * NPRI];     // per-prior cross entropy
__device__ uint8_t g_ct[BATCH * NPRI];     // matched class (0 = background)
__device__ int     g_npos[BATCH];
__device__ float   g_loc[BATCH];           // per-image SmoothL1 sum over positives
__device__ float   g_posce[BATCH];
__device__ float   g_negsum[BATCH];

// ---------------- block reduce helpers (deterministic fixed trees) ----------
template<int NW>
__device__ __forceinline__ float brSumF(float v, float* s) {
    int lane = threadIdx.x & 31, wid = threadIdx.x >> 5;
    #pragma unroll
    for (int o = 16; o; o >>= 1) v += __shfl_xor_sync(0xFFFFFFFFu, v, o);
    if (lane == 0) s[wid] = v;
    __syncthreads();
    if (wid == 0) {
        float r = (lane < NW) ? s[lane] : 0.f;
        #pragma unroll
        for (int o = 16; o; o >>= 1) r += __shfl_xor_sync(0xFFFFFFFFu, r, o);
        if (lane == 0) s[0] = r;
    }
    __syncthreads();
    float r = s[0];
    __syncthreads();
    return r;
}

template<int NW>
__device__ __forceinline__ int brSumI(int v, int* s) {
    int lane = threadIdx.x & 31, wid = threadIdx.x >> 5;
    #pragma unroll
    for (int o = 16; o; o >>= 1) v += __shfl_xor_sync(0xFFFFFFFFu, v, o);
    if (lane == 0) s[wid] = v;
    __syncthreads();
    if (wid == 0) {
        int r = (lane < NW) ? s[lane] : 0;
        #pragma unroll
        for (int o = 16; o; o >>= 1) r += __shfl_xor_sync(0xFFFFFFFFu, r, o);
        if (lane == 0) s[0] = r;
    }
    __syncthreads();
    int r = s[0];
    __syncthreads();
    return r;
}

__device__ __forceinline__ float smooth_l1(float x) {
    float a = fabsf(x);
    return (a < 1.f) ? 0.5f * a * a : a - 0.5f;
}

// ---------------- kernel 1: matching + loc loss ------------------------------
// one block per image, 512 threads
__global__ __launch_bounds__(512)
void k_match(const float* __restrict__ loc_preds,
             const float* __restrict__ boxes,
             const int*   __restrict__ labels,
             const float* __restrict__ priors) {
    const int b   = blockIdx.x;
    const int tid = threadIdx.x;

    __shared__ unsigned long long s_warp[16][16];   // per-warp per-truth best prior
    __shared__ unsigned long long s_best[16];
    __shared__ float   s_btov[NPRI];
    __shared__ uint8_t s_bti[NPRI];
    __shared__ float   s_truth[NOBJ][4];
    __shared__ int     s_lab[NOBJ];
    __shared__ float   s_redf[16];
    __shared__ int     s_redi[16];

    if (tid < NOBJ * 4) ((float*)s_truth)[tid] = boxes[b * NOBJ * 4 + tid];
    if (tid < NOBJ)     s_lab[tid] = labels[b * NOBJ + tid];
    __syncthreads();

    // best prior per truth: packed (iou_bits << 32) | (0xFFFFFFFF - p)
    // -> max picks higher iou; on tie, smaller p (matching argmax first-index)
    unsigned long long loc16[NOBJ];
    #pragma unroll
    for (int o = 0; o < NOBJ; o++) loc16[o] = 0ULL;

    for (int p = tid; p < NPRI; p += 512) {
        float4 pr = ((const float4*)priors)[p];
        float px1 = pr.x - pr.z * 0.5f, py1 = pr.y - pr.w * 0.5f;
        float px2 = pr.x + pr.z * 0.5f, py2 = pr.y + pr.w * 0.5f;
        float area_p = pr.z * pr.w;
        float bestv = -1.0f; int besto = 0;
        #pragma unroll
        for (int o = 0; o < NOBJ; o++) {
            float tx1 = s_truth[o][0], ty1 = s_truth[o][1];
            float tx2 = s_truth[o][2], ty2 = s_truth[o][3];
            float ix = fmaxf(fminf(tx2, px2) - fmaxf(tx1, px1), 0.f);
            float iy = fmaxf(fminf(ty2, py2) - fmaxf(ty1, py1), 0.f);
            float inter  = ix * iy;
            float area_t = (tx2 - tx1) * (ty2 - ty1);
            float iou = inter / (area_t + area_p - inter);
            if (iou > bestv) { bestv = iou; besto = o; }   // strict > : first index on tie
            unsigned long long pk =
                ((unsigned long long)__float_as_uint(iou) << 32) |
                (unsigned)(0xFFFFFFFFu - (unsigned)p);
            loc16[o] = (pk > loc16[o]) ? pk : loc16[o];
        }
        s_btov[p] = bestv;
        s_bti[p]  = (uint8_t)besto;
    }

    // reduce per-truth best prior across threads
    #pragma unroll
    for (int o = 0; o < NOBJ; o++) {
        unsigned long long v = loc16[o];
        #pragma unroll
        for (int off = 16; off; off >>= 1) {
            unsigned long long u = __shfl_xor_sync(0xFFFFFFFFu, v, off);
            v = (u > v) ? u : v;
        }
        if ((tid & 31) == 0) s_warp[tid >> 5][o] = v;
    }
    __syncthreads();
    if (tid < NOBJ) {
        unsigned long long m = 0ULL;
        #pragma unroll
        for (int w = 0; w < 16; w++) {
            unsigned long long u = s_warp[w][tid];
            m = (u > m) ? u : m;
        }
        s_best[tid] = m;
    }
    __syncthreads();
    if (tid == 0) {
        // sequential force-assign (last truth wins on duplicates, like scatter)
        for (int o = 0; o < NOBJ; o++) {
            unsigned p = 0xFFFFFFFFu - (unsigned)(s_best[o] & 0xFFFFFFFFu);
            s_btov[p] = 2.0f;
            s_bti[p]  = (uint8_t)o;
        }
    }
    __syncthreads();

    int   npos   = 0;
    float locsum = 0.f;
    for (int p = tid; p < NPRI; p += 512) {
        float ov = s_btov[p];
        int   o  = s_bti[p];
        int   ct = (ov < THRESH) ? 0 : (s_lab[o] + 1);
        g_ct[b * NPRI + p] = (uint8_t)ct;
        if (ct > 0) {
            npos++;
            float4 pr = ((const float4*)priors)[p];
            float tx1 = s_truth[o][0], ty1 = s_truth[o][1];
            float tx2 = s_truth[o][2], ty2 = s_truth[o][3];
            float g0 = ((tx1 + tx2) * 0.5f - pr.x) / (0.1f * pr.z);
            float g1 = ((ty1 + ty2) * 0.5f - pr.y) / (0.1f * pr.w);
            float g2 = __logf((tx2 - tx1) / pr.z) * 5.0f;   // / 0.2
            float g3 = __logf((ty2 - ty1) / pr.w) * 5.0f;
            float4 lp = ((const float4*)loc_preds)[b * NPRI + p];
            locsum += smooth_l1(lp.x - g0) + smooth_l1(lp.y - g1)
                    + smooth_l1(lp.z - g2) + smooth_l1(lp.w - g3);
        }
    }
    int   npT = brSumI<16>(npos, s_redi);
    float lcT = brSumF<16>(locsum, s_redf);
    if (tid == 0) { g_npos[b] = npT; g_loc[b] = lcT; }
}

// ---------------- kernel 2: per-prior cross entropy --------------------------
// One block = 256 rows = 256*21 floats = 21504 bytes, staged through shared
// with fully coalesced float4 loads. BATCH*NPRI = 1117696 divides by 256
// exactly, and 21504 % 16 == 0, so no tail/bounds handling is needed.
__global__ __launch_bounds__(256)
void k_ce(const float* __restrict__ conf) {
    __shared__ float s_rows[256 * NCLS];   // 21504 bytes
    const int tid  = threadIdx.x;
    const int base = blockIdx.x * 256;     // first row of this block

    // stage: 1344 float4 = 256 rows
    const float4* src = (const float4*)(conf + (size_t)base * NCLS);
    float4* dst = (float4*)s_rows;
    #pragma unroll
    for (int i = 0; i < 6; i++) {
        int j = tid + i * 256;
        if (j < (256 * NCLS) / 4) dst[j] = src[j];
    }
    __syncthreads();

    const int idx = base + tid;
    const int ct  = g_ct[idx];
    const float* v = s_rows + tid * NCLS;  // stride 21 words: conflict-free
    float m = v[0];
    #pragma unroll
    for (int c = 1; c < NCLS; c++) m = fmaxf(m, v[c]);
    float s = 0.f, xt = 0.f;
    #pragma unroll
    for (int c = 0; c < NCLS; c++) {
        s += __expf(v[c] - m);
        if (c == ct) xt = v[c];
    }
    g_ce[idx] = m + __logf(s) - xt;
}

// ---------------- kernel 3: hard-negative top-K via radix select -------------
// one block per image, 1024 threads
__global__ __launch_bounds__(1024)
void k_select() {
    const int b   = blockIdx.x;
    const int tid = threadIdx.x;
    __shared__ float s_ce[NPRI];
    __shared__ float s_redf[32];
    __shared__ int   s_redi[32];

    float posce = 0.f;
    for (int p = tid; p < NPRI; p += 1024) {
        float ce = g_ce[b * NPRI + p];
        if (g_ct[b * NPRI + p] > 0) { posce += ce; ce = 0.f; }   // neg_loss = where(pos,0,ce)
        s_ce[p] = ce;
    }
    float pcT = brSumF<32>(posce, s_redf);
    if (tid == 0) g_posce[b] = pcT;
    __syncthreads();

    int K = NEGPOS * g_npos[b];
    if (K > NPRI) K = NPRI;

    float negsum = 0.f;
    if (K > 0) {
        // exact K-th largest via bit bisection (ce >= 0 -> uint order == float order)
        unsigned prefix = 0u;
        for (int bit = 30; bit >= 0; bit--) {
            unsigned cand = prefix | (1u << bit);
            int cnt = 0;
            for (int p = tid; p < NPRI; p += 1024)
                if (__float_as_uint(s_ce[p]) >= cand) cnt++;
            cnt = brSumI<32>(cnt, s_redi);
            if (cnt >= K) prefix = cand;
        }
        float vK = __uint_as_float(prefix);   // K-th largest value
        float sgt = 0.f; int cgt = 0;
        for (int p = tid; p < NPRI; p += 1024) {
            float v = s_ce[p];
            if (v > vK) { sgt += v; cgt++; }
        }
        sgt = brSumF<32>(sgt, s_redf);
        cgt = brSumI<32>(cgt, s_redi);
        negsum = sgt + (float)(K - cgt) * vK;   // ties included exactly
    }
    if (tid == 0) g_negsum[b] = negsum;
}

// ---------------- kernel 4: final combine ------------------------------------
__global__ __launch_bounds__(128)
void k_final(float* __restrict__ out) {
    __shared__ float s_redf[8];
    const int tid = threadIdx.x;
    float np = 0.f, lc = 0.f, pc = 0.f, ns = 0.f;
    if (tid < BATCH) {
        np = (float)g_npos[tid];
        lc = g_loc[tid];
        pc = g_posce[tid];
        ns = g_negsum[tid];
    }
    float npT = brSumF<4>(np, s_redf);
    float lcT = brSumF<4>(lc, s_redf);
    float pcT = brSumF<4>(pc, s_redf);
    float nsT = brSumF<4>(ns, s_redf);
    if (tid == 0) {
        float conf_loss = (pcT + nsT) / (npT + 1e-7f);
        float loc_loss  = lcT / (4.0f * npT);
        out[0] = conf_loss + loc_loss;
    }
}

// ---------------- launch ------------------------------------------------------
extern "C" void kernel_launch(void* const* d_in, const int* in_sizes, int n_in,
                              void* d_out, int out_size) {
    const float* loc_preds  = (const float*)d_in[0];
    const float* conf_preds = (const float*)d_in[1];
    const float* boxes      = (const float*)d_in[2];
    const int*   labels     = (const int*)d_in[3];
    const float* priors     = (const float*)d_in[4];
    float* out = (float*)d_out;

    k_match<<<BATCH, 512>>>(loc_preds, boxes, labels, priors);
    k_ce<<<(BATCH * NPRI) / 256, 256>>>(conf_preds);
    k_select<<<BATCH, 1024>>>();
    k_final<<<1, 128>>>(out);
    (void)in_sizes; (void)n_in; (void)out_size;
}

// round 3
// speedup vs baseline: 1.1442x; 1.1442x over previous
#include <cuda_runtime.h>
#include <cstdint>

#define BATCH 128
#define NPRI  8732
#define NOBJ  16
#define NCLS  21
#define THRESH 0.5f
#define NSLICE 4
#define SLICE  2183     // 8732 / 4 exactly
#define CEB    35       // ce blocks per image (35*256 >= 8732)

// ---------------- scratch (static device globals; zero-initialized) ----------
__device__ float              g_btov[BATCH * NPRI];
__device__ uint8_t            g_bti [BATCH * NPRI];
__device__ uint8_t            g_ct  [BATCH * NPRI];
__device__ uint8_t            g_of  [BATCH * NPRI];
__device__ float              g_ce  [BATCH * NPRI];
__device__ unsigned long long g_best[BATCH * NOBJ];  // re-zeroed by k3 each launch
__device__ int                g_npos[BATCH];         // re-zeroed by k3 each launch
__device__ float              g_nposf[BATCH];
__device__ float              g_locs[BATCH];
__device__ float              g_pces[BATCH];
__device__ float              g_negs[BATCH];
__device__ unsigned int       g_ticket;              // reset by last block each launch

// ---------------- helpers -----------------------------------------------------
__device__ __forceinline__ float sl1(float x) {
    float a = fabsf(x);
    return (a < 1.f) ? 0.5f * a * a : a - 0.5f;
}

// deterministic block sum, up to 32 warps
__device__ __forceinline__ float brSumF(float v, float* s) {
    int lane = threadIdx.x & 31, wid = threadIdx.x >> 5;
    int nw = (blockDim.x + 31) >> 5;
    #pragma unroll
    for (int o = 16; o; o >>= 1) v += __shfl_xor_sync(0xFFFFFFFFu, v, o);
    if (lane == 0) s[wid] = v;
    __syncthreads();
    if (wid == 0) {
        float r = (lane < nw) ? s[lane] : 0.f;
        #pragma unroll
        for (int o = 16; o; o >>= 1) r += __shfl_xor_sync(0xFFFFFFFFu, r, o);
        if (lane == 0) s[0] = r;
    }
    __syncthreads();
    float r = s[0];
    __syncthreads();
    return r;
}

__device__ __forceinline__ int brSumI(int v, int* s) {
    int lane = threadIdx.x & 31, wid = threadIdx.x >> 5;
    int nw = (blockDim.x + 31) >> 5;
    #pragma unroll
    for (int o = 16; o; o >>= 1) v += __shfl_xor_sync(0xFFFFFFFFu, v, o);
    if (lane == 0) s[wid] = v;
    __syncthreads();
    if (wid == 0) {
        int r = (lane < nw) ? s[lane] : 0;
        #pragma unroll
        for (int o = 16; o; o >>= 1) r += __shfl_xor_sync(0xFFFFFFFFu, r, o);
        if (lane == 0) s[0] = r;
    }
    __syncthreads();
    int r = s[0];
    __syncthreads();
    return r;
}

// ---------------- K1: IoU + per-prior / per-truth argmax ----------------------
// 512 blocks = 4 slices per image, 256 threads. Division-free tracking;
// exactly one div.rn per prior (value semantics identical to reference).
__global__ __launch_bounds__(256)
void k1_iou(const float* __restrict__ boxes, const float* __restrict__ priors) {
    const int b   = blockIdx.x >> 2;
    const int s   = blockIdx.x & 3;
    const int tid = threadIdx.x;
    const int lo  = s * SLICE;
    const int hi  = lo + SLICE;

    __shared__ float s_tx1[NOBJ], s_ty1[NOBJ], s_tx2[NOBJ], s_ty2[NOBJ], s_ta[NOBJ];
    __shared__ unsigned long long s_red[NOBJ][8];

    if (tid < NOBJ) {
        float x1 = boxes[(b * NOBJ + tid) * 4 + 0];
        float y1 = boxes[(b * NOBJ + tid) * 4 + 1];
        float x2 = boxes[(b * NOBJ + tid) * 4 + 2];
        float y2 = boxes[(b * NOBJ + tid) * 4 + 3];
        s_tx1[tid] = x1; s_ty1[tid] = y1; s_tx2[tid] = x2; s_ty2[tid] = y2;
        s_ta[tid] = (x2 - x1) * (y2 - y1);
    }
    __syncthreads();

    // per-truth best (inter, den, p); compare by cross-mult, strict > keeps
    // first (smallest) p within the ascending per-thread stride.
    float    bi[NOBJ], bd[NOBJ];
    unsigned bp[NOBJ];
    #pragma unroll
    for (int o = 0; o < NOBJ; o++) { bi[o] = 0.f; bd[o] = 1.f; bp[o] = (unsigned)(lo + tid); }

    for (int p = lo + tid; p < hi; p += 256) {
        float4 pr = ((const float4*)priors)[p];
        float hw = 0.5f * pr.z, hh = 0.5f * pr.w;
        float px1 = pr.x - hw, py1 = pr.y - hh, px2 = pr.x + hw, py2 = pr.y + hh;
        float ap = pr.z * pr.w;
        float pi = 0.f, pd = 1.f; int po = 0;
        #pragma unroll
        for (int o = 0; o < NOBJ; o++) {
            float ix = fminf(s_tx2[o], px2) - fmaxf(s_tx1[o], px1);
            float iy = fminf(s_ty2[o], py2) - fmaxf(s_ty1[o], py1);
            ix = fmaxf(ix, 0.f); iy = fmaxf(iy, 0.f);
            float inter = ix * iy;
            float den   = s_ta[o] + ap - inter;
            // per-prior argmax over truths (first index on tie)
            bool gt = inter * pd > pi * den;
            pi = gt ? inter : pi;  pd = gt ? den : pd;  po = gt ? o : po;
            // per-truth max over priors
            bool g2 = inter * bd[o] > bi[o] * den;
            bi[o] = g2 ? inter : bi[o];  bd[o] = g2 ? den : bd[o];
            bp[o] = g2 ? (unsigned)p : bp[o];
        }
        float ov = pi / pd;   // single exact division per prior
        g_btov[b * NPRI + p] = ov;
        g_bti [b * NPRI + p] = (uint8_t)po;
    }

    int lane = tid & 31, wid = tid >> 5;
    #pragma unroll
    for (int o = 0; o < NOBJ; o++) {
        float q = bi[o] / bd[o];
        unsigned long long key =
            ((unsigned long long)__float_as_uint(q) << 32) |
            (unsigned)(0xFFFFFFFFu - bp[o]);    // tie -> smaller p wins
        #pragma unroll
        for (int off = 16; off; off >>= 1) {
            unsigned long long u = __shfl_xor_sync(0xFFFFFFFFu, key, off);
            key = (u > key) ? u : key;
        }
        if (lane == 0) s_red[o][wid] = key;
    }
    __syncthreads();
    if (tid < NOBJ) {
        unsigned long long m = 0ULL;
        #pragma unroll
        for (int w = 0; w < 8; w++) {
            unsigned long long u = s_red[tid][w];
            m = (u > m) ? u : m;
        }
        atomicMax(&g_best[b * NOBJ + tid], m);   // order-independent merge
    }
}

// ---------------- K2: force-assign + conf target + cross entropy --------------
// grid = BATCH*CEB blocks, 256 threads; conf rows staged via coalesced float4.
__global__ __launch_bounds__(256)
void k2_ce(const float* __restrict__ conf, const int* __restrict__ labels) {
    const int blk = blockIdx.x;
    const int b   = blk / CEB;
    const int t   = blk % CEB;
    const int tid = threadIdx.x;
    const int r0  = t * 256;
    const int nr  = min(256, NPRI - r0);

    __shared__ float    s_rows[256 * NCLS];
    __shared__ int      s_lab[NOBJ];
    __shared__ unsigned s_fp[NOBJ];
    __shared__ int      s_wc[8];

    if (tid < NOBJ) {
        s_lab[tid] = labels[b * NOBJ + tid];
        s_fp[tid]  = 0xFFFFFFFFu - (unsigned)(g_best[b * NOBJ + tid] & 0xFFFFFFFFULL);
    }
    const int nf4 = nr * NCLS / 4;   // nr*21 always divisible by 4 here
    const float4* src = (const float4*)(conf + ((size_t)b * NPRI + r0) * NCLS);
    #pragma unroll
    for (int i = 0; i < 6; i++) {
        int j = tid + i * 256;
        if (j < nf4) ((float4*)s_rows)[j] = src[j];
    }
    __syncthreads();

    int isp = 0;
    if (tid < nr) {
        int p = r0 + tid;
        size_t idx = (size_t)b * NPRI + p;
        float ov = g_btov[idx];
        int   o  = g_bti[idx];
        #pragma unroll
        for (int oo = 0; oo < NOBJ; oo++) {       // ascending: last truth wins
            bool f = (s_fp[oo] == (unsigned)p);
            ov = f ? 2.0f : ov;
            o  = f ? oo : o;
        }
        int ct = (ov < THRESH) ? 0 : (s_lab[o] + 1);
        g_ct[idx] = (uint8_t)ct;
        g_of[idx] = (uint8_t)o;
        isp = (ct > 0);
        const float* v = s_rows + tid * NCLS;     // stride 21: conflict-free
        float m = v[0];
        #pragma unroll
        for (int c = 1; c < NCLS; c++) m = fmaxf(m, v[c]);
        float ssum = 0.f;
        #pragma unroll
        for (int c = 0; c < NCLS; c++) ssum += __expf(v[c] - m);
        g_ce[idx] = m + __logf(ssum) - v[ct];
    }
    unsigned bal = __ballot_sync(0xFFFFFFFFu, isp);
    if ((tid & 31) == 0) s_wc[tid >> 5] = __popc(bal);
    __syncthreads();
    if (tid == 0) {
        int c = 0;
        #pragma unroll
        for (int w = 0; w < 8; w++) c += s_wc[w];
        atomicAdd(&g_npos[b], c);                 // int: deterministic
    }
}

// ---------------- K3: loc loss + register-resident top-K + fused final --------
__global__ __launch_bounds__(1024)
void k3_select(const float* __restrict__ loc_preds,
               const float* __restrict__ boxes,
               const float* __restrict__ priors,
               float* __restrict__ out) {
    const int b   = blockIdx.x;
    const int tid = threadIdx.x;

    __shared__ float s_tx1[NOBJ], s_ty1[NOBJ], s_tx2[NOBJ], s_ty2[NOBJ];
    __shared__ float s_redf[32];
    __shared__ int   s_redi[32];
    __shared__ int   s_wc[32];
    __shared__ int   s_bc[4];

    if (tid < NOBJ) {
        s_tx1[tid] = boxes[(b * NOBJ + tid) * 4 + 0];
        s_ty1[tid] = boxes[(b * NOBJ + tid) * 4 + 1];
        s_tx2[tid] = boxes[(b * NOBJ + tid) * 4 + 2];
        s_ty2[tid] = boxes[(b * NOBJ + tid) * 4 + 3];
    }
    if (tid == 0) s_bc[0] = g_npos[b];
    __syncthreads();
    const int npos = s_bc[0];

    unsigned u[9];
    float posce = 0.f, locsum = 0.f;
    #pragma unroll
    for (int i = 0; i < 9; i++) {
        int p = tid + i * 1024;
        u[i] = 0u;
        if (p < NPRI) {
            size_t idx = (size_t)b * NPRI + p;
            float ce = g_ce[idx];
            if (g_ct[idx] > 0) {
                posce += ce;
                int o = g_of[idx];
                float4 pr = ((const float4*)priors)[p];
                float tx1 = s_tx1[o], ty1 = s_ty1[o], tx2 = s_tx2[o], ty2 = s_ty2[o];
                float g0 = ((tx1 + tx2) * 0.5f - pr.x) / (0.1f * pr.z);
                float g1 = ((ty1 + ty2) * 0.5f - pr.y) / (0.1f * pr.w);
                float g2 = __logf((tx2 - tx1) / pr.z) * 5.0f;
                float g3 = __logf((ty2 - ty1) / pr.w) * 5.0f;
                float4 lp = ((const float4*)loc_preds)[(size_t)b * NPRI + p];
                locsum += sl1(lp.x - g0) + sl1(lp.y - g1)
                        + sl1(lp.z - g2) + sl1(lp.w - g3);
            } else {
                u[i] = __float_as_uint(ce);   // negatives only; ce >= 0
            }
        }
    }

    float pcT = brSumF(posce, s_redf);
    float lcT = brSumF(locsum, s_redf);

    int K = 3 * npos; if (K > NPRI) K = NPRI;
    float negsum = 0.f;
    if (K > 0) {
        unsigned prefix = 0u;
        for (int bit = 30; bit >= 0; bit--) {
            unsigned cand = prefix | (1u << bit);
            int c = 0;
            #pragma unroll
            for (int i = 0; i < 9; i++)
                c += __popc(__ballot_sync(0xFFFFFFFFu, u[i] >= cand));
            if ((tid & 31) == 0) s_wc[tid >> 5] = c;
            __syncthreads();
            if (tid < 32) {
                int t2 = s_wc[tid];
                #pragma unroll
                for (int off = 16; off; off >>= 1)
                    t2 += __shfl_xor_sync(0xFFFFFFFFu, t2, off);
                if (tid == 0) s_bc[1] = t2;
            }
            __syncthreads();
            if (s_bc[1] >= K) prefix = cand;
        }
        float vK = __uint_as_float(prefix);       // exact K-th largest
        float sgt = 0.f; int cgt = 0;
        #pragma unroll
        for (int i = 0; i < 9; i++) {
            float v = __uint_as_float(u[i]);
            if (v > vK) { sgt += v; cgt++; }
        }
        sgt = brSumF(sgt, s_redf);
        cgt = brSumI(cgt, s_redi);
        negsum = sgt + (float)(K - cgt) * vK;     // ties handled exactly
    }

    if (tid == 0) {
        g_locs[b]  = lcT;
        g_pces[b]  = pcT;
        g_negs[b]  = negsum;
        g_nposf[b] = (float)npos;
    }
    // re-zero per-image scratch for the next graph replay
    if (tid < NOBJ) g_best[b * NOBJ + tid] = 0ULL;
    if (tid == 32)  g_npos[b] = 0;

    __threadfence();
    __syncthreads();
    if (tid == 0) {
        unsigned old = atomicAdd(&g_ticket, 1u);
        s_bc[2] = (old == BATCH - 1) ? 1 : 0;
    }
    __syncthreads();

    if (s_bc[2]) {   // last block: final reduction over images
        float np = 0.f, lc = 0.f, pc = 0.f, ns = 0.f;
        if (tid < BATCH) {
            np = __ldcg(&g_nposf[tid]);
            lc = __ldcg(&g_locs[tid]);
            pc = __ldcg(&g_pces[tid]);
            ns = __ldcg(&g_negs[tid]);
        }
        np = brSumF(np, s_redf);
        lc = brSumF(lc, s_redf);
        pc = brSumF(pc, s_redf);
        ns = brSumF(ns, s_redf);
        if (tid == 0) {
            out[0] = (pc + ns) / (np + 1e-7f) + lc / (4.0f * np);
            g_ticket = 0u;                        // reset for next replay
        }
    }
}

// ---------------- launch ------------------------------------------------------
extern "C" void kernel_launch(void* const* d_in, const int* in_sizes, int n_in,
                              void* d_out, int out_size) {
    const float* loc_preds  = (const float*)d_in[0];
    const float* conf_preds = (const float*)d_in[1];
    const float* boxes      = (const float*)d_in[2];
    const int*   labels     = (const int*)d_in[3];
    const float* priors     = (const float*)d_in[4];
    float* out = (float*)d_out;

    k1_iou<<<BATCH * NSLICE, 256>>>(boxes, priors);
    k2_ce<<<BATCH * CEB, 256>>>(conf_preds, labels);
    k3_select<<<BATCH, 1024>>>(loc_preds, boxes, priors, out);
    (void)in_sizes; (void)n_in; (void)out_size;
}

// round 4
// speedup vs baseline: 1.3129x; 1.1475x over previous
#include <cuda_runtime.h>
#include <cstdint>

#define BATCH 128
#define NPRI  8732
#define NOBJ  16
#define NCLS  21
#define THRESH 0.5f
#define NSLICE 4
#define SLICE  2183     // 8732 / 4 exactly
#define CEB    35       // ce blocks per image (35*256 >= 8732)

// ---------------- scratch (static device globals; zero-initialized) ----------
__device__ float              g_btov[BATCH * NPRI];
__device__ uint8_t            g_bti [BATCH * NPRI];
__device__ uint8_t            g_ct  [BATCH * NPRI];
__device__ uint8_t            g_of  [BATCH * NPRI];
__device__ float              g_ce  [BATCH * NPRI];
__device__ unsigned long long g_best[BATCH * NOBJ];  // re-zeroed by k3 each launch
__device__ int                g_npos[BATCH];         // re-zeroed by k3 each launch
__device__ float              g_nposf[BATCH];
__device__ float              g_locs[BATCH];
__device__ float              g_pces[BATCH];
__device__ float              g_negs[BATCH];
__device__ unsigned int       g_ticket;              // reset by last block each launch

// ---------------- helpers -----------------------------------------------------
__device__ __forceinline__ float sl1(float x) {
    float a = fabsf(x);
    return (a < 1.f) ? 0.5f * a * a : a - 0.5f;
}

__device__ __forceinline__ float brSumF(float v, float* s) {
    int lane = threadIdx.x & 31, wid = threadIdx.x >> 5;
    int nw = (blockDim.x + 31) >> 5;
    #pragma unroll
    for (int o = 16; o; o >>= 1) v += __shfl_xor_sync(0xFFFFFFFFu, v, o);
    if (lane == 0) s[wid] = v;
    __syncthreads();
    if (wid == 0) {
        float r = (lane < nw) ? s[lane] : 0.f;
        #pragma unroll
        for (int o = 16; o; o >>= 1) r += __shfl_xor_sync(0xFFFFFFFFu, r, o);
        if (lane == 0) s[0] = r;
    }
    __syncthreads();
    float r = s[0];
    __syncthreads();
    return r;
}

__device__ __forceinline__ int brSumI(int v, int* s) {
    int lane = threadIdx.x & 31, wid = threadIdx.x >> 5;
    int nw = (blockDim.x + 31) >> 5;
    #pragma unroll
    for (int o = 16; o; o >>= 1) v += __shfl_xor_sync(0xFFFFFFFFu, v, o);
    if (lane == 0) s[wid] = v;
    __syncthreads();
    if (wid == 0) {
        int r = (lane < nw) ? s[lane] : 0;
        #pragma unroll
        for (int o = 16; o; o >>= 1) r += __shfl_xor_sync(0xFFFFFFFFu, r, o);
        if (lane == 0) s[0] = r;
    }
    __syncthreads();
    int r = s[0];
    __syncthreads();
    return r;
}

// ---------------- K1: IoU + argmaxes (approx-compare, exact threshold value) --
// 512 blocks = 4 slices per image, 256 threads, <=128 regs (2 blocks/SM).
__global__ __launch_bounds__(256, 2)
void k1_iou(const float* __restrict__ boxes, const float* __restrict__ priors) {
    const int b   = blockIdx.x >> 2;
    const int s   = blockIdx.x & 3;
    const int tid = threadIdx.x;
    const int lo  = s * SLICE;
    const int hi  = lo + SLICE;

    __shared__ float4 s_t[NOBJ];     // truth boxes (x1,y1,x2,y2)
    __shared__ float  s_ta[NOBJ];    // truth areas
    __shared__ unsigned long long s_red[NOBJ][8];

    if (tid < NOBJ) {
        float4 t = ((const float4*)boxes)[b * NOBJ + tid];
        s_t[tid]  = t;
        s_ta[tid] = (t.z - t.x) * (t.w - t.y);
    }
    __syncthreads();

    // per-truth best approx IoU + prior index (ascending p, strict > keeps first)
    float    bv[NOBJ];
    unsigned bp[NOBJ];
    #pragma unroll
    for (int o = 0; o < NOBJ; o++) { bv[o] = -1.f; bp[o] = 0u; }

    for (int p = lo + tid; p < hi; p += 256) {
        float4 pr = ((const float4*)priors)[p];
        float hw = 0.5f * pr.z, hh = 0.5f * pr.w;
        float px1 = pr.x - hw, py1 = pr.y - hh, px2 = pr.x + hw, py2 = pr.y + hh;
        float ap = pr.z * pr.w;
        float pv = -1.f; int po = 0;
        #pragma unroll
        for (int o = 0; o < NOBJ; o++) {
            float4 t = s_t[o];
            float ix = fmaxf(fminf(t.z, px2) - fmaxf(t.x, px1), 0.f);
            float iy = fmaxf(fminf(t.w, py2) - fmaxf(t.y, py1), 0.f);
            float inter = ix * iy;
            float den   = (s_ta[o] + ap) - inter;
            float v     = inter * __frcp_rn(den);   // approx: ordering only
            bool g1 = v > pv;                       // first truth on tie
            pv = g1 ? v : pv;  po = g1 ? o : po;
            bool g2 = v > bv[o];                    // first prior on tie
            bv[o] = g2 ? v : bv[o];
            bp[o] = g2 ? (unsigned)p : bp[o];
        }
        // exact IoU for the winning truth only (threshold semantics exact)
        {
            float4 t = s_t[po];
            float ix = fmaxf(fminf(t.z, px2) - fmaxf(t.x, px1), 0.f);
            float iy = fmaxf(fminf(t.w, py2) - fmaxf(t.y, py1), 0.f);
            float inter = ix * iy;
            float den   = (s_ta[po] + ap) - inter;
            g_btov[b * NPRI + p] = inter / den;     // div.rn, once per prior
            g_bti [b * NPRI + p] = (uint8_t)po;
        }
    }

    int lane = tid & 31, wid = tid >> 5;
    #pragma unroll
    for (int o = 0; o < NOBJ; o++) {
        unsigned long long key =
            ((unsigned long long)__float_as_uint(bv[o]) << 32) |
            (unsigned)(0xFFFFFFFFu - bp[o]);        // tie -> smaller p wins
        #pragma unroll
        for (int off = 16; off; off >>= 1) {
            unsigned long long u = __shfl_xor_sync(0xFFFFFFFFu, key, off);
            key = (u > key) ? u : key;
        }
        if (lane == 0) s_red[o][wid] = key;
    }
    __syncthreads();
    if (tid < NOBJ) {
        unsigned long long m = 0ULL;
        #pragma unroll
        for (int w = 0; w < 8; w++) {
            unsigned long long u = s_red[tid][w];
            m = (u > m) ? u : m;
        }
        atomicMax(&g_best[b * NOBJ + tid], m);      // order-independent merge
    }
}

// ---------------- K2: force-assign + conf target + cross entropy --------------
__global__ __launch_bounds__(256)
void k2_ce(const float* __restrict__ conf, const int* __restrict__ labels) {
    const int blk = blockIdx.x;
    const int b   = blk / CEB;
    const int t   = blk % CEB;
    const int tid = threadIdx.x;
    const int r0  = t * 256;
    const int nr  = min(256, NPRI - r0);

    __shared__ float    s_rows[256 * NCLS];
    __shared__ int      s_lab[NOBJ];
    __shared__ unsigned s_fp[NOBJ];
    __shared__ int      s_wc[8];

    if (tid < NOBJ) {
        s_lab[tid] = labels[b * NOBJ + tid];
        s_fp[tid]  = 0xFFFFFFFFu - (unsigned)(g_best[b * NOBJ + tid] & 0xFFFFFFFFULL);
    }
    const int nf4 = nr * NCLS / 4;
    const float4* src = (const float4*)(conf + ((size_t)b * NPRI + r0) * NCLS);
    #pragma unroll
    for (int i = 0; i < 6; i++) {
        int j = tid + i * 256;
        if (j < nf4) ((float4*)s_rows)[j] = src[j];
    }
    __syncthreads();

    int isp = 0;
    if (tid < nr) {
        int p = r0 + tid;
        size_t idx = (size_t)b * NPRI + p;
        float ov = g_btov[idx];
        int   o  = g_bti[idx];
        #pragma unroll
        for (int oo = 0; oo < NOBJ; oo++) {          // ascending: last truth wins
            bool f = (s_fp[oo] == (unsigned)p);
            ov = f ? 2.0f : ov;
            o  = f ? oo : o;
        }
        int ct = (ov < THRESH) ? 0 : (s_lab[o] + 1);
        g_ct[idx] = (uint8_t)ct;
        g_of[idx] = (uint8_t)o;
        isp = (ct > 0);
        const float* v = s_rows + tid * NCLS;        // stride 21: conflict-free
        float m = v[0];
        #pragma unroll
        for (int c = 1; c < NCLS; c++) m = fmaxf(m, v[c]);
        float ssum = 0.f;
        #pragma unroll
        for (int c = 0; c < NCLS; c++) ssum += __expf(v[c] - m);
        g_ce[idx] = m + __logf(ssum) - v[ct];
    }
    unsigned bal = __ballot_sync(0xFFFFFFFFu, isp);
    if ((tid & 31) == 0) s_wc[tid >> 5] = __popc(bal);
    __syncthreads();
    if (tid == 0) {
        int c = 0;
        #pragma unroll
        for (int w = 0; w < 8; w++) c += s_wc[w];
        atomicAdd(&g_npos[b], c);
    }
}

// ---------------- K3: loc loss + register-resident top-K + fused final --------
__global__ __launch_bounds__(1024)
void k3_select(const float* __restrict__ loc_preds,
               const float* __restrict__ boxes,
               const float* __restrict__ priors,
               float* __restrict__ out) {
    const int b   = blockIdx.x;
    const int tid = threadIdx.x;

    __shared__ float s_tx1[NOBJ], s_ty1[NOBJ], s_tx2[NOBJ], s_ty2[NOBJ];
    __shared__ float s_redf[32];
    __shared__ int   s_redi[32];
    __shared__ int   s_wc[32];
    __shared__ int   s_bc[4];

    if (tid < NOBJ) {
        s_tx1[tid] = boxes[(b * NOBJ + tid) * 4 + 0];
        s_ty1[tid] = boxes[(b * NOBJ + tid) * 4 + 1];
        s_tx2[tid] = boxes[(b * NOBJ + tid) * 4 + 2];
        s_ty2[tid] = boxes[(b * NOBJ + tid) * 4 + 3];
    }
    if (tid == 0) s_bc[0] = g_npos[b];
    __syncthreads();
    const int npos = s_bc[0];

    unsigned u[9];
    float posce = 0.f, locsum = 0.f;
    #pragma unroll
    for (int i = 0; i < 9; i++) {
        int p = tid + i * 1024;
        u[i] = 0u;
        if (p < NPRI) {
            size_t idx = (size_t)b * NPRI + p;
            float ce = g_ce[idx];
            if (g_ct[idx] > 0) {
                posce += ce;
                int o = g_of[idx];
                float4 pr = ((const float4*)priors)[p];
                float tx1 = s_tx1[o], ty1 = s_ty1[o], tx2 = s_tx2[o], ty2 = s_ty2[o];
                float g0 = ((tx1 + tx2) * 0.5f - pr.x) / (0.1f * pr.z);
                float g1 = ((ty1 + ty2) * 0.5f - pr.y) / (0.1f * pr.w);
                float g2 = __logf((tx2 - tx1) / pr.z) * 5.0f;
                float g3 = __logf((ty2 - ty1) / pr.w) * 5.0f;
                float4 lp = ((const float4*)loc_preds)[(size_t)b * NPRI + p];
                locsum += sl1(lp.x - g0) + sl1(lp.y - g1)
                        + sl1(lp.z - g2) + sl1(lp.w - g3);
            } else {
                u[i] = __float_as_uint(ce);   // negatives only; ce >= 0
            }
        }
    }

    float pcT = brSumF(posce, s_redf);
    float lcT = brSumF(locsum, s_redf);

    int K = 3 * npos; if (K > NPRI) K = NPRI;
    float negsum = 0.f;
    if (K > 0) {
        unsigned prefix = 0u;
        for (int bit = 30; bit >= 0; bit--) {
            unsigned cand = prefix | (1u << bit);
            int c = 0;
            #pragma unroll
            for (int i = 0; i < 9; i++)
                c += __popc(__ballot_sync(0xFFFFFFFFu, u[i] >= cand));
            if ((tid & 31) == 0) s_wc[tid >> 5] = c;
            __syncthreads();
            if (tid < 32) {
                int t2 = s_wc[tid];
                #pragma unroll
                for (int off = 16; off; off >>= 1)
                    t2 += __shfl_xor_sync(0xFFFFFFFFu, t2, off);
                if (tid == 0) s_bc[1] = t2;
            }
            __syncthreads();
            if (s_bc[1] >= K) prefix = cand;
        }
        float vK = __uint_as_float(prefix);
        float sgt = 0.f; int cgt = 0;
        #pragma unroll
        for (int i = 0; i < 9; i++) {
            float v = __uint_as_float(u[i]);
            if (v > vK) { sgt += v; cgt++; }
        }
        sgt = brSumF(sgt, s_redf);
        cgt = brSumI(cgt, s_redi);
        negsum = sgt + (float)(K - cgt) * vK;
    }

    if (tid == 0) {
        g_locs[b]  = lcT;
        g_pces[b]  = pcT;
        g_negs[b]  = negsum;
        g_nposf[b] = (float)npos;
    }
    if (tid < NOBJ) g_best[b * NOBJ + tid] = 0ULL;   // re-zero for graph replay
    if (tid == 32)  g_npos[b] = 0;

    __threadfence();
    __syncthreads();
    if (tid == 0) {
        unsigned old = atomicAdd(&g_ticket, 1u);
        s_bc[2] = (old == BATCH - 1) ? 1 : 0;
    }
    __syncthreads();

    if (s_bc[2]) {
        float np = 0.f, lc = 0.f, pc = 0.f, ns = 0.f;
        if (tid < BATCH) {
            np = __ldcg(&g_nposf[tid]);
            lc = __ldcg(&g_locs[tid]);
            pc = __ldcg(&g_pces[tid]);
            ns = __ldcg(&g_negs[tid]);
        }
        np = brSumF(np, s_redf);
        lc = brSumF(lc, s_redf);
        pc = brSumF(pc, s_redf);
        ns = brSumF(ns, s_redf);
        if (tid == 0) {
            out[0] = (pc + ns) / (np + 1e-7f) + lc / (4.0f * np);
            g_ticket = 0u;
        }
    }
}

// ---------------- launch ------------------------------------------------------
extern "C" void kernel_launch(void* const* d_in, const int* in_sizes, int n_in,
                              void* d_out, int out_size) {
    const float* loc_preds  = (const float*)d_in[0];
    const float* conf_preds = (const float*)d_in[1];
    const float* boxes      = (const float*)d_in[2];
    const int*   labels     = (const int*)d_in[3];
    const float* priors     = (const float*)d_in[4];
    float* out = (float*)d_out;

    k1_iou<<<BATCH * NSLICE, 256>>>(boxes, priors);
    k2_ce<<<BATCH * CEB, 256>>>(conf_preds, labels);
    k3_select<<<BATCH, 1024>>>(loc_preds, boxes, priors, out);
    (void)in_sizes; (void)n_in; (void)out_size;
}